// round 5
// baseline (speedup 1.0000x reference)
#include <cuda_runtime.h>
#include <math.h>
#include <stdint.h>

typedef unsigned long long ull;

// ---------------- packed f32x2 helpers (Blackwell FFMA2) ----------------
__device__ __forceinline__ ull pack2(float lo, float hi) {
    ull r; asm("mov.b64 %0, {%1, %2};" : "=l"(r) : "f"(lo), "f"(hi)); return r;
}
__device__ __forceinline__ float2 unpack2(ull v) {
    float2 f; asm("mov.b64 {%0, %1}, %2;" : "=f"(f.x), "=f"(f.y) : "l"(v)); return f;
}
__device__ __forceinline__ void ffma2(ull& d, ull a, ull b) {
    asm("fma.rn.f32x2 %0, %1, %2, %3;" : "=l"(d) : "l"(a), "l"(b), "l"(d));
}

// ---------------- mma.sync tf32 helpers (sm_80+ baseline; works on sm_103) ----
__device__ __forceinline__ float to_tf32(float x) {
    float r; asm("cvt.rna.tf32.f32 %0, %1;" : "=f"(r) : "f"(x)); return r;
}
__device__ __forceinline__ void mma_tf32(float* c, const uint32_t* a, const uint32_t* b) {
    asm volatile(
        "mma.sync.aligned.m16n8k8.row.col.f32.tf32.tf32.f32 "
        "{%0,%1,%2,%3}, {%4,%5,%6,%7}, {%8,%9}, {%0,%1,%2,%3};"
        : "+f"(c[0]), "+f"(c[1]), "+f"(c[2]), "+f"(c[3])
        : "r"(a[0]), "r"(a[1]), "r"(a[2]), "r"(a[3]), "r"(b[0]), "r"(b[1]));
}

// ---------------- static scratch (no allocations allowed) ----------------
__device__ float g_bufA[16777216];   // 64 MB ping
__device__ float g_bufB[16777216];   // 64 MB pong
__device__ float g_m1[1048576];      // 4*64^3
__device__ float g_m2[131072];       // 4*32^3
__device__ float g_m3[16384];        // 4*16^3
__device__ int   g_cnt[3];
__device__ float g_part[128 * 1024];
__device__ float g_scale[512];
__device__ float g_shift[512];
__device__ float g_ppart[4 * 16 * 512];
__device__ float g_cpart[4 * 16];
__device__ float g_pooled[4 * 512];

#define EPSBN 1e-5f

// ---------------- mask pooling (2x2x2 max) + active count ----------------
template <typename T>
__global__ void pool_mask_kernel(const T* __restrict__ min_, float* __restrict__ mout,
                                 int* __restrict__ cnt, int B, int Dout) {
    int Din = Dout * 2;
    int M = B * Dout * Dout * Dout;
    int site = blockIdx.x * blockDim.x + threadIdx.x;
    int active = 0;
    if (site < M) {
        int ow = site % Dout; int t = site / Dout;
        int oh = t % Dout; t /= Dout;
        int od = t % Dout; int b = t / Dout;
        int iz0 = od * 2, iy0 = oh * 2, ix0 = ow * 2;
        bool a = false;
        #pragma unroll
        for (int dz = 0; dz < 2; dz++)
            #pragma unroll
            for (int dy = 0; dy < 2; dy++)
                #pragma unroll
                for (int dx = 0; dx < 2; dx++) {
                    T v = min_[(((long)(b * Din + iz0 + dz) * Din + iy0 + dy) * Din) + ix0 + dx];
                    a = a || (v != (T)0);
                }
        mout[site] = a ? 1.f : 0.f;
        active = a ? 1 : 0;
    }
    unsigned bal = __ballot_sync(0xffffffffu, active);
    __shared__ int ws[8];
    if ((threadIdx.x & 31) == 0) ws[threadIdx.x >> 5] = __popc(bal);
    __syncthreads();
    if (threadIdx.x == 0) {
        int t = 0;
        for (int i = 0; i < (int)(blockDim.x >> 5); i++) t += ws[i];
        atomicAdd(cnt, t);
    }
}

// ---------------- conv1a ----------------
__global__ void __launch_bounds__(256) conv1a_kernel(
    const float* __restrict__ x, const int* __restrict__ mask,
    const float* __restrict__ w, const float* __restrict__ m1, float* __restrict__ y) {
    __shared__ float wsh[432];
    for (int i = threadIdx.x; i < 432; i += 256) wsh[i] = w[i];
    __syncthreads();
    int site = blockIdx.x * 256 + threadIdx.x;
    int ow = site & 63; int t = site >> 6;
    int oh = t & 63; t >>= 6;
    int od = t & 63; int b = t >> 6;
    float acc[16];
    #pragma unroll
    for (int c = 0; c < 16; c++) acc[c] = 0.f;
    #pragma unroll
    for (int tz = 0; tz < 3; tz++) {
        int iz = od * 2 - 1 + tz;
        if ((unsigned)iz >= 128u) continue;
        #pragma unroll
        for (int ty = 0; ty < 3; ty++) {
            int iy = oh * 2 - 1 + ty;
            if ((unsigned)iy >= 128u) continue;
            #pragma unroll
            for (int tx = 0; tx < 3; tx++) {
                int ix = ow * 2 - 1 + tx;
                if ((unsigned)ix >= 128u) continue;
                int idx = ((b * 128 + iz) * 128 + iy) * 128 + ix;
                if (mask[idx]) {
                    float v = x[idx];
                    int tap = (tz * 3 + ty) * 3 + tx;
                    #pragma unroll
                    for (int c = 0; c < 16; c++) acc[c] += v * wsh[tap * 16 + c];
                }
            }
        }
    }
    float mk = m1[site];
    float* o = y + (long)site * 16;
    #pragma unroll
    for (int q = 0; q < 4; q++) {
        float4 v = make_float4(acc[q*4]*mk, acc[q*4+1]*mk, acc[q*4+2]*mk, acc[q*4+3]*mk);
        *(float4*)(o + q * 4) = v;
    }
}

// ---------------- conv1b: 64^3 16->16, f32x2 ----------------
__global__ void __launch_bounds__(256) conv1b_kernel(
    const float* __restrict__ in, const float* __restrict__ w,
    const float* __restrict__ m, float* __restrict__ out) {
    __shared__ __align__(16) float wsh[6912];
    for (int i = threadIdx.x; i < 6912; i += 256) wsh[i] = w[i];
    __syncthreads();
    int pair = blockIdx.x * 256 + threadIdx.x;
    int s0 = pair * 2;
    int ow = s0 & 63; int t = s0 >> 6;
    int oh = t & 63; t >>= 6;
    int od = t & 63; int b = t >> 6;
    ull acc0p[8], acc1p[8];
    #pragma unroll
    for (int h = 0; h < 8; h++) { acc0p[h] = 0ull; acc1p[h] = 0ull; }
    #pragma unroll
    for (int tz = 0; tz < 3; tz++) {
        int iz = od - 1 + tz;
        if ((unsigned)iz >= 64u) continue;
        #pragma unroll
        for (int ty = 0; ty < 3; ty++) {
            int iy = oh - 1 + ty;
            if ((unsigned)iy >= 64u) continue;
            int rowbase = ((b * 64 + iz) * 64 + iy) * 64;
            #pragma unroll
            for (int tx = 0; tx < 3; tx++) {
                int ix0 = ow - 1 + tx;
                int ix1 = ix0 + 1;
                int tap = (tz * 3 + ty) * 3 + tx;
                const float* wp = wsh + tap * 256;
                bool ok0 = (unsigned)ix0 < 64u;
                bool ok1 = (unsigned)ix1 < 64u;
                float4 v0q[4], v1q[4];
                #pragma unroll
                for (int q = 0; q < 4; q++) {
                    v0q[q] = ok0 ? *(const float4*)(in + (long)(rowbase + ix0) * 16 + q * 4)
                                 : make_float4(0, 0, 0, 0);
                    v1q[q] = ok1 ? *(const float4*)(in + (long)(rowbase + ix1) * 16 + q * 4)
                                 : make_float4(0, 0, 0, 0);
                }
                const float* v0 = (const float*)v0q;
                const float* v1 = (const float*)v1q;
                #pragma unroll
                for (int ci = 0; ci < 16; ci++) {
                    ull a0d = pack2(v0[ci], v0[ci]);
                    ull a1d = pack2(v1[ci], v1[ci]);
                    const ull* wrow = (const ull*)(wp + ci * 16);
                    #pragma unroll
                    for (int h = 0; h < 8; h++) {
                        ull wv = wrow[h];
                        ffma2(acc0p[h], a0d, wv);
                        ffma2(acc1p[h], a1d, wv);
                    }
                }
            }
        }
    }
    float mk0 = m[s0], mk1 = m[s0 + 1];
    #pragma unroll
    for (int q = 0; q < 4; q++) {
        float2 e0 = unpack2(acc0p[2*q]), e1 = unpack2(acc0p[2*q+1]);
        *(float4*)(out + (long)s0 * 16 + q * 4) =
            make_float4(e0.x*mk0, e0.y*mk0, e1.x*mk0, e1.y*mk0);
        float2 f0 = unpack2(acc1p[2*q]), f1 = unpack2(acc1p[2*q+1]);
        *(float4*)(out + (long)(s0 + 1) * 16 + q * 4) =
            make_float4(f0.x*mk1, f0.y*mk1, f1.x*mk1, f1.y*mk1);
    }
}

// ---------------- scalar implicit GEMM (conv2a only, CIN=16) ----------------
template <int CIN, int COUT, int S, int BN>
__global__ void __launch_bounds__(256) conv_igemm2(
    const float* __restrict__ in, const float* __restrict__ w,
    const float* __restrict__ mout, float* __restrict__ out,
    int Din, int Dout) {
    constexpr int BM = 128;
    constexpr int BK = 16;
    constexpr int TN = BN / 16;
    constexpr int KTOT = 27 * CIN;
    __shared__ __align__(16) float As[BK][BM];
    __shared__ __align__(16) float Bs[BK][BN];
    __shared__ int sB[BM], sZ[BM], sY[BM], sX[BM];

    const int tid = threadIdx.x;
    const int m0 = blockIdx.x * BM;
    const int n0 = blockIdx.y * BN;

    if (tid < BM) {
        int mm = m0 + tid;
        int ow = mm % Dout; int t = mm / Dout;
        int oh = t % Dout; t /= Dout;
        int od = t % Dout; int b = t / Dout;
        sB[tid] = b; sZ[tid] = od * S - 1; sY[tid] = oh * S - 1; sX[tid] = ow * S - 1;
    }
    __syncthreads();

    const int am = tid & 127;
    const int ah = tid >> 7;
    const int aBb = sB[am], aZ = sZ[am], aY = sY[am], aX = sX[am];
    const int ty = tid >> 4, tx = tid & 15;

    ull acc[8][TN / 2];
    #pragma unroll
    for (int i = 0; i < 8; i++)
        #pragma unroll
        for (int j = 0; j < TN / 2; j++) acc[i][j] = 0ull;

    float4 aR0, aR1, bR0;

    auto loadA = [&](int k0) {
        int tap = k0 / CIN;
        int ci0 = k0 - tap * CIN + (ah << 3);
        int tz = tap / 9; int tr = tap - tz * 9;
        int tyy = tr / 3; int txx = tr - tyy * 3;
        int iz = aZ + tz, iy = aY + tyy, ix = aX + txx;
        aR0 = make_float4(0, 0, 0, 0);
        aR1 = aR0;
        if ((unsigned)iz < (unsigned)Din && (unsigned)iy < (unsigned)Din &&
            (unsigned)ix < (unsigned)Din) {
            int idx = (((aBb * Din + iz) * Din + iy) * Din + ix) * CIN + ci0;
            aR0 = *(const float4*)(in + idx);
            aR1 = *(const float4*)(in + idx + 4);
        }
    };
    auto storeA = [&]() {
        int kb = ah << 3;
        As[kb + 0][am] = aR0.x; As[kb + 1][am] = aR0.y;
        As[kb + 2][am] = aR0.z; As[kb + 3][am] = aR0.w;
        As[kb + 4][am] = aR1.x; As[kb + 5][am] = aR1.y;
        As[kb + 6][am] = aR1.z; As[kb + 7][am] = aR1.w;
    };
    auto loadB = [&](int k0) {
        int kr = tid >> 4, n4 = (tid & 15) << 2;
        bR0 = *(const float4*)(w + (long)(k0 + kr) * COUT + n0 + n4);
    };
    auto storeB = [&]() {
        int kr = tid >> 4, n4 = (tid & 15) << 2;
        *(float4*)&Bs[kr][n4] = bR0;
    };

    loadA(0); loadB(0);
    storeA(); storeB();
    __syncthreads();

    for (int k0 = 0; k0 < KTOT; k0 += BK) {
        bool more = (k0 + BK) < KTOT;
        if (more) { loadA(k0 + BK); loadB(k0 + BK); }
        #pragma unroll
        for (int kk = 0; kk < BK; kk++) {
            float4 a0 = *(const float4*)&As[kk][ty << 3];
            float4 a1 = *(const float4*)&As[kk][(ty << 3) + 4];
            ull ad[8];
            ad[0] = pack2(a0.x, a0.x); ad[1] = pack2(a0.y, a0.y);
            ad[2] = pack2(a0.z, a0.z); ad[3] = pack2(a0.w, a0.w);
            ad[4] = pack2(a1.x, a1.x); ad[5] = pack2(a1.y, a1.y);
            ad[6] = pack2(a1.z, a1.z); ad[7] = pack2(a1.w, a1.w);
            ull bd[TN / 2];
            #pragma unroll
            for (int j = 0; j < TN / 2; j++)
                bd[j] = *(const ull*)&Bs[kk][tx * TN + (j << 1)];
            #pragma unroll
            for (int i = 0; i < 8; i++)
                #pragma unroll
                for (int j = 0; j < TN / 2; j++)
                    ffma2(acc[i][j], ad[i], bd[j]);
        }
        __syncthreads();
        if (more) { storeA(); storeB(); __syncthreads(); }
    }

    #pragma unroll
    for (int i = 0; i < 8; i++) {
        int mm = m0 + (ty << 3) + i;
        float mk = mout[mm];
        #pragma unroll
        for (int q = 0; q < TN / 4; q++) {
            float2 e0 = unpack2(acc[i][2 * q]);
            float2 e1 = unpack2(acc[i][2 * q + 1]);
            *(float4*)(out + (long)mm * COUT + n0 + tx * TN + 4 * q) =
                make_float4(e0.x * mk, e0.y * mk, e1.x * mk, e1.y * mk);
        }
    }
}

// ---------------- tensor-core tf32 implicit GEMM (conv2b / conv3a / conv3b) ----
// mma.sync m16n8k8 tf32. BM=128, BK=32. Smem stages are stored PRE-PERMUTED into
// fragment layout: A atom (m16 x k8) = 32 lanes x uint4; B atom (k8 x n8) =
// 32 lanes x uint2. Fragment loads are conflict-free vector LDS.
// Requires CIN % 32 == 0 (BK chunk never straddles a 3x3x3 tap).
template <int CIN, int COUT, int S, int BN>
__global__ void __launch_bounds__(256, 1) conv_mma_tf32(
    const float* __restrict__ in, const float* __restrict__ w,
    const float* __restrict__ mout, float* __restrict__ out,
    int Din, int Dout) {
    constexpr int BM = 128;
    constexpr int BK = 32;
    constexpr int T = 27 * CIN / BK;
    constexpr int NTW = BN / 32;           // n-tiles (of 8) per warp
    constexpr int ASZ = 4096;              // floats per A stage (128*32)
    constexpr int BSZ = BN * 32;           // floats per B stage
    constexpr int BQ = BN * 8 / 256;       // B float4 quads per thread per stage

    extern __shared__ __align__(16) char smem[];
    int* sB = (int*)smem;
    int* sZ = sB + 128;
    int* sY = sZ + 128;
    int* sX = sY + 128;
    float* AsP[2] = { (float*)(smem + 2048), (float*)(smem + 2048) + ASZ };
    float* BsP[2] = { (float*)(smem + 2048) + 2 * ASZ,
                      (float*)(smem + 2048) + 2 * ASZ + BSZ };

    const int tid = threadIdx.x;
    const int warp = tid >> 5;
    const int lane = tid & 31;
    const int wm = warp & 1;               // 2 warps along M (64 rows each)
    const int wn = warp >> 1;              // 4 warps along N
    const int m0 = blockIdx.x * BM;
    const int n0 = blockIdx.y * BN;

    if (tid < BM) {
        int mm = m0 + tid;
        int ow = mm % Dout; int t = mm / Dout;
        int oh = t % Dout; t /= Dout;
        int od = t % Dout; int b = t / Dout;
        sB[tid] = b; sZ[tid] = od * S - 1; sY[tid] = oh * S - 1; sX[tid] = ow * S - 1;
    }
    __syncthreads();

    float acc[4][NTW][4];
    #pragma unroll
    for (int i = 0; i < 4; i++)
        #pragma unroll
        for (int j = 0; j < NTW; j++)
            #pragma unroll
            for (int q = 0; q < 4; q++) acc[i][j][q] = 0.f;

    float4 ra[4], rb[BQ];

    auto loadStage = [&](int st) {
        int k0 = st * BK;
        int tap = k0 / CIN;
        int ci0 = k0 - tap * CIN;
        int tz = tap / 9; int tr = tap - tz * 9;
        int tyy = tr / 3; int txx = tr - tyy * 3;
        #pragma unroll
        for (int r = 0; r < 4; r++) {
            int qi = tid + 256 * r;            // 0..1023
            int m = qi >> 3, kq = qi & 7;
            int iz = sZ[m] + tz, iy = sY[m] + tyy, ix = sX[m] + txx;
            float4 v = make_float4(0, 0, 0, 0);
            if ((unsigned)iz < (unsigned)Din && (unsigned)iy < (unsigned)Din &&
                (unsigned)ix < (unsigned)Din) {
                v = *(const float4*)(in +
                    (size_t)(((sB[m] * Din + iz) * Din + iy) * Din + ix) * CIN +
                    ci0 + kq * 4);
            }
            ra[r] = v;
        }
        #pragma unroll
        for (int r = 0; r < BQ; r++) {
            int qi = tid + 256 * r;            // 0..BN*8-1
            int k = qi / (BN / 4);
            int nq = qi % (BN / 4);
            rb[r] = *(const float4*)(w + (size_t)(k0 + k) * COUT + n0 + nq * 4);
        }
    };
    auto storeStage = [&](int s) {
        float* A = AsP[s];
        #pragma unroll
        for (int r = 0; r < 4; r++) {
            int qi = tid + 256 * r;
            int m = qi >> 3, kq = qi & 7;
            int mt = m >> 4, rr = m & 15;
            int ks = kq >> 1;
            int reg = (rr >> 3) + ((kq & 1) << 1);
            int g = rr & 7;
            float* p = A + ((mt * 4 + ks) << 7) + g * 16 + reg;
            p[0]  = to_tf32(ra[r].x);
            p[4]  = to_tf32(ra[r].y);
            p[8]  = to_tf32(ra[r].z);
            p[12] = to_tf32(ra[r].w);
        }
        float* Bp = BsP[s];
        #pragma unroll
        for (int r = 0; r < BQ; r++) {
            int qi = tid + 256 * r;
            int k = qi / (BN / 4);
            int nq = qi % (BN / 4);
            int n4 = nq * 4;
            int nt = n4 >> 3, g0 = n4 & 7;
            int t = k & 3, reg = (k >> 2) & 1, ks = k >> 3;
            float* p = Bp + ((nt * 4 + ks) << 6) + g0 * 8 + t * 2 + reg;
            p[0]  = to_tf32(rb[r].x);
            p[8]  = to_tf32(rb[r].y);
            p[16] = to_tf32(rb[r].z);
            p[24] = to_tf32(rb[r].w);
        }
    };
    auto compute = [&](int s) {
        const float* A = AsP[s];
        const float* Bp = BsP[s];
        #pragma unroll
        for (int ks = 0; ks < 4; ks++) {
            uint4 af[4];
            uint2 bf[NTW];
            #pragma unroll
            for (int i = 0; i < 4; i++)
                af[i] = *(const uint4*)(A + (((wm * 4 + i) * 4 + ks) << 7) + lane * 4);
            #pragma unroll
            for (int j = 0; j < NTW; j++)
                bf[j] = *(const uint2*)(Bp + (((wn * NTW + j) * 4 + ks) << 6) + lane * 2);
            #pragma unroll
            for (int i = 0; i < 4; i++)
                #pragma unroll
                for (int j = 0; j < NTW; j++)
                    mma_tf32(acc[i][j], (const uint32_t*)&af[i], (const uint32_t*)&bf[j]);
        }
    };

    loadStage(0);
    storeStage(0);
    __syncthreads();

    for (int st = 0; st < T; st++) {
        int s = st & 1;
        bool more = (st + 1) < T;
        if (more) loadStage(st + 1);
        compute(s);
        __syncthreads();
        if (more) { storeStage(s ^ 1); __syncthreads(); }
    }

    // epilogue
    const int g = lane >> 2, t = lane & 3;
    #pragma unroll
    for (int i = 0; i < 4; i++) {
        int row0 = m0 + wm * 64 + i * 16 + g;
        int row1 = row0 + 8;
        float mk0 = mout[row0], mk1 = mout[row1];
        #pragma unroll
        for (int j = 0; j < NTW; j++) {
            int col = n0 + (wn * NTW + j) * 8 + t * 2;
            *(float2*)(out + (size_t)row0 * COUT + col) =
                make_float2(acc[i][j][0] * mk0, acc[i][j][1] * mk0);
            *(float2*)(out + (size_t)row1 * COUT + col) =
                make_float2(acc[i][j][2] * mk1, acc[i][j][3] * mk1);
        }
    }
}

// ---------------- BN reductions ----------------
template <int C>
__global__ void __launch_bounds__(256) bn_reduce(const float* __restrict__ y, int nsites,
                                                 float* __restrict__ part) {
    constexpr int GP = C / 4;
    constexpr int NG = 256 / GP;
    int tid = threadIdx.x;
    int g = tid / GP;
    int lane = tid - g * GP;
    int c0 = lane * 4;
    float s0 = 0, s1 = 0, s2 = 0, s3 = 0;
    float q0 = 0, q1 = 0, q2 = 0, q3 = 0;
    for (int site = blockIdx.x * NG + g; site < nsites; site += gridDim.x * NG) {
        float4 v = *(const float4*)(y + (long)site * C + c0);
        s0 += v.x; s1 += v.y; s2 += v.z; s3 += v.w;
        q0 += v.x * v.x; q1 += v.y * v.y; q2 += v.z * v.z; q3 += v.w * v.w;
    }
    __shared__ float sm[NG][C];
    __shared__ float sq[NG][C];
    sm[g][c0 + 0] = s0; sm[g][c0 + 1] = s1; sm[g][c0 + 2] = s2; sm[g][c0 + 3] = s3;
    sq[g][c0 + 0] = q0; sq[g][c0 + 1] = q1; sq[g][c0 + 2] = q2; sq[g][c0 + 3] = q3;
    __syncthreads();
    for (int c = tid; c < C; c += 256) {
        float a = 0, b = 0;
        #pragma unroll 4
        for (int gg = 0; gg < NG; gg++) { a += sm[gg][c]; b += sq[gg][c]; }
        part[blockIdx.x * (2 * C) + c] = a;
        part[blockIdx.x * (2 * C) + C + c] = b;
    }
}

template <int C>
__global__ void __launch_bounds__(512) bn_finalize(
        const float* __restrict__ part, const int* __restrict__ cntp,
        const float* __restrict__ gamma, const float* __restrict__ beta,
        float* __restrict__ scale, float* __restrict__ shift) {
    constexpr int R = 512 / C;
    int c = threadIdx.x % C;
    int r = threadIdx.x / C;
    float s = 0, q = 0;
    for (int nb = r; nb < 128; nb += R) {
        s += part[nb * 2 * C + c];
        q += part[nb * 2 * C + C + c];
    }
    __shared__ float ss[512], qq[512];
    ss[threadIdx.x] = s; qq[threadIdx.x] = q;
    __syncthreads();
    if (r == 0) {
        for (int rr = 1; rr < R; rr++) { s += ss[rr * C + c]; q += qq[rr * C + c]; }
        float cnt = (float)cntp[0];
        float mean = s / cnt;
        float var = q / cnt - mean * mean;
        float sc = gamma[c] * rsqrtf(var + EPSBN);
        scale[c] = sc;
        shift[c] = beta[c] - mean * sc;
    }
}

template <int C>
__global__ void bn_apply(float* __restrict__ y, const float* __restrict__ m,
                         const float* __restrict__ scale, const float* __restrict__ shift,
                         int nsites) {
    __shared__ float sc[C], sh[C];
    for (int i = threadIdx.x; i < C; i += blockDim.x) { sc[i] = scale[i]; sh[i] = shift[i]; }
    __syncthreads();
    long total = (long)nsites * (C / 4);
    long i = (long)blockIdx.x * blockDim.x + threadIdx.x;
    if (i >= total) return;
    float4 v = ((float4*)y)[i];
    int cq = (int)(i % (C / 4)) * 4;
    float mk = m[i / (C / 4)];
    float a;
    a = v.x * sc[cq + 0] + sh[cq + 0]; v.x = (a > 0.f ? a : expm1f(a)) * mk;
    a = v.y * sc[cq + 1] + sh[cq + 1]; v.y = (a > 0.f ? a : expm1f(a)) * mk;
    a = v.z * sc[cq + 2] + sh[cq + 2]; v.z = (a > 0.f ? a : expm1f(a)) * mk;
    a = v.w * sc[cq + 3] + sh[cq + 3]; v.w = (a > 0.f ? a : expm1f(a)) * mk;
    ((float4*)y)[i] = v;
}

// ---------------- global pooling ----------------
__global__ void pool_partial(const float* __restrict__ y, const float* __restrict__ m3,
                             float* __restrict__ ppart, float* __restrict__ cpart) {
    int b = blockIdx.x;
    int g = blockIdx.y;
    int c = threadIdx.x;
    float s = 0;
    int sbase = g * 256;
    for (int k = 0; k < 256; k++) s += y[((long)(b * 4096 + sbase + k)) * 512 + c];
    ppart[(b * 16 + g) * 512 + c] = s;
    __shared__ float red[512];
    red[c] = (c < 256) ? m3[b * 4096 + sbase + c] : 0.f;
    __syncthreads();
    for (int st = 256; st > 0; st >>= 1) {
        if (c < st) red[c] += red[c + st];
        __syncthreads();
    }
    if (c == 0) cpart[b * 16 + g] = red[0];
}

__global__ void pool_final(const float* __restrict__ ppart, const float* __restrict__ cpart,
                           float* __restrict__ pooled) {
    int b = blockIdx.x;
    int c = threadIdx.x;
    float s = 0, cnt = 0;
    for (int g = 0; g < 16; g++) {
        s += ppart[(b * 16 + g) * 512 + c];
        cnt += cpart[b * 16 + g];
    }
    pooled[b * 512 + c] = s / cnt;
}

// ---------------- heads ----------------
__global__ void heads_kernel(const float* __restrict__ pooled,
                             const float* __restrict__ wm, const float* __restrict__ bm,
                             const float* __restrict__ wv, const float* __restrict__ bv,
                             float* __restrict__ out) {
    int b = blockIdx.x;
    int j = threadIdx.x;
    __shared__ float p[512];
    p[j] = pooled[b * 512 + j];
    __syncthreads();
    float sm_ = bm[j], sv = bv[j];
    for (int c = 0; c < 512; c++) {
        float pv = p[c];
        sm_ += pv * wm[c * 512 + j];
        sv += pv * wv[c * 512 + j];
    }
    out[b * 512 + j] = sm_;
    out[2048 + b * 512 + j] = sv;
}

// ---------------- host launcher ----------------
extern "C" void kernel_launch(void* const* d_in, const int* in_sizes, int n_in,
                              void* d_out, int out_size) {
    const float* x    = (const float*)d_in[0];
    const int*   mask = (const int*)d_in[1];
    const float* w1a = (const float*)d_in[2];
    const float* g1a = (const float*)d_in[3];
    const float* b1a = (const float*)d_in[4];
    const float* w1b = (const float*)d_in[5];
    const float* g1b = (const float*)d_in[6];
    const float* b1b = (const float*)d_in[7];
    const float* w2a = (const float*)d_in[8];
    const float* g2a = (const float*)d_in[9];
    const float* b2a = (const float*)d_in[10];
    const float* w2b = (const float*)d_in[11];
    const float* g2b = (const float*)d_in[12];
    const float* b2b = (const float*)d_in[13];
    const float* w3a = (const float*)d_in[14];
    const float* g3a = (const float*)d_in[15];
    const float* b3a = (const float*)d_in[16];
    const float* w3b = (const float*)d_in[17];
    const float* g3b = (const float*)d_in[18];
    const float* b3b = (const float*)d_in[19];
    const float* wm  = (const float*)d_in[20];
    const float* bm  = (const float*)d_in[21];
    const float* wv  = (const float*)d_in[22];
    const float* bv  = (const float*)d_in[23];

    float *bufA, *bufB, *m1, *m2, *m3, *part, *scale, *shift, *ppart, *cpart, *pooled;
    int* cnt;
    cudaGetSymbolAddress((void**)&bufA, g_bufA);
    cudaGetSymbolAddress((void**)&bufB, g_bufB);
    cudaGetSymbolAddress((void**)&m1, g_m1);
    cudaGetSymbolAddress((void**)&m2, g_m2);
    cudaGetSymbolAddress((void**)&m3, g_m3);
    cudaGetSymbolAddress((void**)&cnt, g_cnt);
    cudaGetSymbolAddress((void**)&part, g_part);
    cudaGetSymbolAddress((void**)&scale, g_scale);
    cudaGetSymbolAddress((void**)&shift, g_shift);
    cudaGetSymbolAddress((void**)&ppart, g_ppart);
    cudaGetSymbolAddress((void**)&cpart, g_cpart);
    cudaGetSymbolAddress((void**)&pooled, g_pooled);

    // dynamic smem: 2048 (coords) + 2*16384 (A stages) + 2*BN*128 (B stages)
    const int SMM64  = 2048 + 2 * 16384 + 2 * 64 * 128;    // 51200
    const int SMM128 = 2048 + 2 * 16384 + 2 * 128 * 128;   // 67584
    cudaFuncSetAttribute(conv_mma_tf32<64, 64, 1, 64>,
                         cudaFuncAttributeMaxDynamicSharedMemorySize, SMM64);
    cudaFuncSetAttribute(conv_mma_tf32<64, 512, 2, 128>,
                         cudaFuncAttributeMaxDynamicSharedMemorySize, SMM128);
    cudaFuncSetAttribute(conv_mma_tf32<512, 512, 1, 128>,
                         cudaFuncAttributeMaxDynamicSharedMemorySize, SMM128);

    cudaMemsetAsync(cnt, 0, 3 * sizeof(int));

    // ---- block 1 ----
    pool_mask_kernel<int><<<4096, 256>>>(mask, m1, cnt + 0, 4, 64);
    conv1a_kernel<<<4096, 256>>>(x, mask, w1a, m1, bufA);
    bn_reduce<16><<<128, 256>>>(bufA, 1048576, part);
    bn_finalize<16><<<1, 512>>>(part, cnt + 0, g1a, b1a, scale, shift);
    bn_apply<16><<<(1048576 * 4 + 255) / 256, 256>>>(bufA, m1, scale, shift, 1048576);
    conv1b_kernel<<<2048, 256>>>(bufA, w1b, m1, bufB);
    bn_reduce<16><<<128, 256>>>(bufB, 1048576, part);
    bn_finalize<16><<<1, 512>>>(part, cnt + 0, g1b, b1b, scale, shift);
    bn_apply<16><<<(1048576 * 4 + 255) / 256, 256>>>(bufB, m1, scale, shift, 1048576);

    // ---- block 2 ----
    pool_mask_kernel<float><<<512, 256>>>(m1, m2, cnt + 1, 4, 32);
    conv_igemm2<16, 64, 2, 64><<<dim3(1024, 1), 256>>>(bufB, w2a, m2, bufA, 64, 32);
    bn_reduce<64><<<128, 256>>>(bufA, 131072, part);
    bn_finalize<64><<<1, 512>>>(part, cnt + 1, g2a, b2a, scale, shift);
    bn_apply<64><<<(131072 * 16 + 255) / 256, 256>>>(bufA, m2, scale, shift, 131072);
    conv_mma_tf32<64, 64, 1, 64><<<dim3(1024, 1), 256, SMM64>>>(bufA, w2b, m2, bufB, 32, 32);
    bn_reduce<64><<<128, 256>>>(bufB, 131072, part);
    bn_finalize<64><<<1, 512>>>(part, cnt + 1, g2b, b2b, scale, shift);
    bn_apply<64><<<(131072 * 16 + 255) / 256, 256>>>(bufB, m2, scale, shift, 131072);

    // ---- block 3 ----
    pool_mask_kernel<float><<<64, 256>>>(m2, m3, cnt + 2, 4, 16);
    conv_mma_tf32<64, 512, 2, 128><<<dim3(128, 4), 256, SMM128>>>(bufB, w3a, m3, bufA, 32, 16);
    bn_reduce<512><<<128, 256>>>(bufA, 16384, part);
    bn_finalize<512><<<1, 512>>>(part, cnt + 2, g3a, b3a, scale, shift);
    bn_apply<512><<<(16384 * 128 + 255) / 256, 256>>>(bufA, m3, scale, shift, 16384);
    conv_mma_tf32<512, 512, 1, 128><<<dim3(128, 4), 256, SMM128>>>(bufA, w3b, m3, bufB, 16, 16);
    bn_reduce<512><<<128, 256>>>(bufB, 16384, part);
    bn_finalize<512><<<1, 512>>>(part, cnt + 2, g3b, b3b, scale, shift);
    bn_apply<512><<<(16384 * 128 + 255) / 256, 256>>>(bufB, m3, scale, shift, 16384);

    // ---- global pooling + heads ----
    pool_partial<<<dim3(4, 16), 512>>>(bufB, m3, ppart, cpart);
    pool_final<<<4, 512>>>(ppart, cpart, pooled);
    heads_kernel<<<4, 512>>>(pooled, wm, bm, wv, bv, (float*)d_out);

    (void)in_sizes; (void)n_in; (void)out_size;
}

// round 6
// speedup vs baseline: 2.0481x; 2.0481x over previous
#include <cuda_runtime.h>
#include <cuda_fp16.h>
#include <math.h>
#include <stdint.h>

typedef unsigned long long ull;

// ---------------- packed f32x2 helpers (Blackwell FFMA2) ----------------
__device__ __forceinline__ ull pack2(float lo, float hi) {
    ull r; asm("mov.b64 %0, {%1, %2};" : "=l"(r) : "f"(lo), "f"(hi)); return r;
}
__device__ __forceinline__ float2 unpack2(ull v) {
    float2 f; asm("mov.b64 {%0, %1}, %2;" : "=f"(f.x), "=f"(f.y) : "l"(v)); return f;
}
__device__ __forceinline__ void ffma2(ull& d, ull a, ull b) {
    asm("fma.rn.f32x2 %0, %1, %2, %3;" : "=l"(d) : "l"(a), "l"(b), "l"(d));
}

// ---------------- fp16 mma.sync helpers ----------------
__device__ __forceinline__ uint32_t packh2(float lo, float hi) {
    __half2 h = __floats2half2_rn(lo, hi);
    return *(uint32_t*)&h;
}
__device__ __forceinline__ void mma_f16(float* c, const uint32_t* a, const uint32_t* b) {
    asm volatile(
        "mma.sync.aligned.m16n8k16.row.col.f32.f16.f16.f32 "
        "{%0,%1,%2,%3}, {%4,%5,%6,%7}, {%8,%9}, {%0,%1,%2,%3};"
        : "+f"(c[0]), "+f"(c[1]), "+f"(c[2]), "+f"(c[3])
        : "r"(a[0]), "r"(a[1]), "r"(a[2]), "r"(a[3]), "r"(b[0]), "r"(b[1]));
}

// ---------------- static scratch ----------------
__device__ float g_bufA[16777216];
__device__ float g_bufB[16777216];
__device__ float g_m1[1048576];
__device__ float g_m2[131072];
__device__ float g_m3[16384];
__device__ int   g_cnt[3];
__device__ float g_part[128 * 1024];
__device__ float g_scale[512];
__device__ float g_shift[512];
__device__ float g_ppart[4 * 16 * 512];
__device__ float g_cpart[4 * 16];
__device__ float g_pooled[4 * 512];

#define EPSBN 1e-5f

// ---------------- mask pooling + active count ----------------
template <typename T>
__global__ void pool_mask_kernel(const T* __restrict__ min_, float* __restrict__ mout,
                                 int* __restrict__ cnt, int B, int Dout) {
    int Din = Dout * 2;
    int M = B * Dout * Dout * Dout;
    int site = blockIdx.x * blockDim.x + threadIdx.x;
    int active = 0;
    if (site < M) {
        int ow = site % Dout; int t = site / Dout;
        int oh = t % Dout; t /= Dout;
        int od = t % Dout; int b = t / Dout;
        int iz0 = od * 2, iy0 = oh * 2, ix0 = ow * 2;
        bool a = false;
        #pragma unroll
        for (int dz = 0; dz < 2; dz++)
            #pragma unroll
            for (int dy = 0; dy < 2; dy++)
                #pragma unroll
                for (int dx = 0; dx < 2; dx++) {
                    T v = min_[(((long)(b * Din + iz0 + dz) * Din + iy0 + dy) * Din) + ix0 + dx];
                    a = a || (v != (T)0);
                }
        mout[site] = a ? 1.f : 0.f;
        active = a ? 1 : 0;
    }
    unsigned bal = __ballot_sync(0xffffffffu, active);
    __shared__ int ws[8];
    if ((threadIdx.x & 31) == 0) ws[threadIdx.x >> 5] = __popc(bal);
    __syncthreads();
    if (threadIdx.x == 0) {
        int t = 0;
        for (int i = 0; i < (int)(blockDim.x >> 5); i++) t += ws[i];
        atomicAdd(cnt, t);
    }
}

// ---------------- conv1a ----------------
__global__ void __launch_bounds__(256) conv1a_kernel(
    const float* __restrict__ x, const int* __restrict__ mask,
    const float* __restrict__ w, const float* __restrict__ m1, float* __restrict__ y) {
    __shared__ float wsh[432];
    for (int i = threadIdx.x; i < 432; i += 256) wsh[i] = w[i];
    __syncthreads();
    int site = blockIdx.x * 256 + threadIdx.x;
    int ow = site & 63; int t = site >> 6;
    int oh = t & 63; t >>= 6;
    int od = t & 63; int b = t >> 6;
    float acc[16];
    #pragma unroll
    for (int c = 0; c < 16; c++) acc[c] = 0.f;
    #pragma unroll
    for (int tz = 0; tz < 3; tz++) {
        int iz = od * 2 - 1 + tz;
        if ((unsigned)iz >= 128u) continue;
        #pragma unroll
        for (int ty = 0; ty < 3; ty++) {
            int iy = oh * 2 - 1 + ty;
            if ((unsigned)iy >= 128u) continue;
            #pragma unroll
            for (int tx = 0; tx < 3; tx++) {
                int ix = ow * 2 - 1 + tx;
                if ((unsigned)ix >= 128u) continue;
                int idx = ((b * 128 + iz) * 128 + iy) * 128 + ix;
                if (mask[idx]) {
                    float v = x[idx];
                    int tap = (tz * 3 + ty) * 3 + tx;
                    #pragma unroll
                    for (int c = 0; c < 16; c++) acc[c] += v * wsh[tap * 16 + c];
                }
            }
        }
    }
    float mk = m1[site];
    float* o = y + (long)site * 16;
    #pragma unroll
    for (int q = 0; q < 4; q++) {
        float4 v = make_float4(acc[q*4]*mk, acc[q*4+1]*mk, acc[q*4+2]*mk, acc[q*4+3]*mk);
        *(float4*)(o + q * 4) = v;
    }
}

// ---------------- conv1b: f32x2 ----------------
__global__ void __launch_bounds__(256) conv1b_kernel(
    const float* __restrict__ in, const float* __restrict__ w,
    const float* __restrict__ m, float* __restrict__ out) {
    __shared__ __align__(16) float wsh[6912];
    for (int i = threadIdx.x; i < 6912; i += 256) wsh[i] = w[i];
    __syncthreads();
    int pair = blockIdx.x * 256 + threadIdx.x;
    int s0 = pair * 2;
    int ow = s0 & 63; int t = s0 >> 6;
    int oh = t & 63; t >>= 6;
    int od = t & 63; int b = t >> 6;
    ull acc0p[8], acc1p[8];
    #pragma unroll
    for (int h = 0; h < 8; h++) { acc0p[h] = 0ull; acc1p[h] = 0ull; }
    #pragma unroll
    for (int tz = 0; tz < 3; tz++) {
        int iz = od - 1 + tz;
        if ((unsigned)iz >= 64u) continue;
        #pragma unroll
        for (int ty = 0; ty < 3; ty++) {
            int iy = oh - 1 + ty;
            if ((unsigned)iy >= 64u) continue;
            int rowbase = ((b * 64 + iz) * 64 + iy) * 64;
            #pragma unroll
            for (int tx = 0; tx < 3; tx++) {
                int ix0 = ow - 1 + tx;
                int ix1 = ix0 + 1;
                int tap = (tz * 3 + ty) * 3 + tx;
                const float* wp = wsh + tap * 256;
                bool ok0 = (unsigned)ix0 < 64u;
                bool ok1 = (unsigned)ix1 < 64u;
                float4 v0q[4], v1q[4];
                #pragma unroll
                for (int q = 0; q < 4; q++) {
                    v0q[q] = ok0 ? *(const float4*)(in + (long)(rowbase + ix0) * 16 + q * 4)
                                 : make_float4(0, 0, 0, 0);
                    v1q[q] = ok1 ? *(const float4*)(in + (long)(rowbase + ix1) * 16 + q * 4)
                                 : make_float4(0, 0, 0, 0);
                }
                const float* v0 = (const float*)v0q;
                const float* v1 = (const float*)v1q;
                #pragma unroll
                for (int ci = 0; ci < 16; ci++) {
                    ull a0d = pack2(v0[ci], v0[ci]);
                    ull a1d = pack2(v1[ci], v1[ci]);
                    const ull* wrow = (const ull*)(wp + ci * 16);
                    #pragma unroll
                    for (int h = 0; h < 8; h++) {
                        ull wv = wrow[h];
                        ffma2(acc0p[h], a0d, wv);
                        ffma2(acc1p[h], a1d, wv);
                    }
                }
            }
        }
    }
    float mk0 = m[s0], mk1 = m[s0 + 1];
    #pragma unroll
    for (int q = 0; q < 4; q++) {
        float2 e0 = unpack2(acc0p[2*q]), e1 = unpack2(acc0p[2*q+1]);
        *(float4*)(out + (long)s0 * 16 + q * 4) =
            make_float4(e0.x*mk0, e0.y*mk0, e1.x*mk0, e1.y*mk0);
        float2 f0 = unpack2(acc1p[2*q]), f1 = unpack2(acc1p[2*q+1]);
        *(float4*)(out + (long)(s0 + 1) * 16 + q * 4) =
            make_float4(f0.x*mk1, f0.y*mk1, f1.x*mk1, f1.y*mk1);
    }
}

// ---------------- scalar implicit GEMM (conv2a, CIN=16) ----------------
template <int CIN, int COUT, int S, int BN>
__global__ void __launch_bounds__(256) conv_igemm2(
    const float* __restrict__ in, const float* __restrict__ w,
    const float* __restrict__ mout, float* __restrict__ out,
    int Din, int Dout) {
    constexpr int BM = 128;
    constexpr int BK = 16;
    constexpr int TN = BN / 16;
    constexpr int KTOT = 27 * CIN;
    __shared__ __align__(16) float As[BK][BM];
    __shared__ __align__(16) float Bs[BK][BN];
    __shared__ int sB[BM], sZ[BM], sY[BM], sX[BM];

    const int tid = threadIdx.x;
    const int m0 = blockIdx.x * BM;
    const int n0 = blockIdx.y * BN;

    if (tid < BM) {
        int mm = m0 + tid;
        int ow = mm % Dout; int t = mm / Dout;
        int oh = t % Dout; t /= Dout;
        int od = t % Dout; int b = t / Dout;
        sB[tid] = b; sZ[tid] = od * S - 1; sY[tid] = oh * S - 1; sX[tid] = ow * S - 1;
    }
    __syncthreads();

    const int am = tid & 127;
    const int ah = tid >> 7;
    const int aBb = sB[am], aZ = sZ[am], aY = sY[am], aX = sX[am];
    const int ty = tid >> 4, tx = tid & 15;

    ull acc[8][TN / 2];
    #pragma unroll
    for (int i = 0; i < 8; i++)
        #pragma unroll
        for (int j = 0; j < TN / 2; j++) acc[i][j] = 0ull;

    float4 aR0, aR1, bR0;

    auto loadA = [&](int k0) {
        int tap = k0 / CIN;
        int ci0 = k0 - tap * CIN + (ah << 3);
        int tz = tap / 9; int tr = tap - tz * 9;
        int tyy = tr / 3; int txx = tr - tyy * 3;
        int iz = aZ + tz, iy = aY + tyy, ix = aX + txx;
        aR0 = make_float4(0, 0, 0, 0);
        aR1 = aR0;
        if ((unsigned)iz < (unsigned)Din && (unsigned)iy < (unsigned)Din &&
            (unsigned)ix < (unsigned)Din) {
            int idx = (((aBb * Din + iz) * Din + iy) * Din + ix) * CIN + ci0;
            aR0 = *(const float4*)(in + idx);
            aR1 = *(const float4*)(in + idx + 4);
        }
    };
    auto storeA = [&]() {
        int kb = ah << 3;
        As[kb + 0][am] = aR0.x; As[kb + 1][am] = aR0.y;
        As[kb + 2][am] = aR0.z; As[kb + 3][am] = aR0.w;
        As[kb + 4][am] = aR1.x; As[kb + 5][am] = aR1.y;
        As[kb + 6][am] = aR1.z; As[kb + 7][am] = aR1.w;
    };
    auto loadB = [&](int k0) {
        int kr = tid >> 4, n4 = (tid & 15) << 2;
        bR0 = *(const float4*)(w + (long)(k0 + kr) * COUT + n0 + n4);
    };
    auto storeB = [&]() {
        int kr = tid >> 4, n4 = (tid & 15) << 2;
        *(float4*)&Bs[kr][n4] = bR0;
    };

    loadA(0); loadB(0);
    storeA(); storeB();
    __syncthreads();

    for (int k0 = 0; k0 < KTOT; k0 += BK) {
        bool more = (k0 + BK) < KTOT;
        if (more) { loadA(k0 + BK); loadB(k0 + BK); }
        #pragma unroll
        for (int kk = 0; kk < BK; kk++) {
            float4 a0 = *(const float4*)&As[kk][ty << 3];
            float4 a1 = *(const float4*)&As[kk][(ty << 3) + 4];
            ull ad[8];
            ad[0] = pack2(a0.x, a0.x); ad[1] = pack2(a0.y, a0.y);
            ad[2] = pack2(a0.z, a0.z); ad[3] = pack2(a0.w, a0.w);
            ad[4] = pack2(a1.x, a1.x); ad[5] = pack2(a1.y, a1.y);
            ad[6] = pack2(a1.z, a1.z); ad[7] = pack2(a1.w, a1.w);
            ull bd[TN / 2];
            #pragma unroll
            for (int j = 0; j < TN / 2; j++)
                bd[j] = *(const ull*)&Bs[kk][tx * TN + (j << 1)];
            #pragma unroll
            for (int i = 0; i < 8; i++)
                #pragma unroll
                for (int j = 0; j < TN / 2; j++)
                    ffma2(acc[i][j], ad[i], bd[j]);
        }
        __syncthreads();
        if (more) { storeA(); storeB(); __syncthreads(); }
    }

    #pragma unroll
    for (int i = 0; i < 8; i++) {
        int mm = m0 + (ty << 3) + i;
        float mk = mout[mm];
        #pragma unroll
        for (int q = 0; q < TN / 4; q++) {
            float2 e0 = unpack2(acc[i][2 * q]);
            float2 e1 = unpack2(acc[i][2 * q + 1]);
            *(float4*)(out + (long)mm * COUT + n0 + tx * TN + 4 * q) =
                make_float4(e0.x * mk, e0.y * mk, e1.x * mk, e1.y * mk);
        }
    }
}

// ---------------- fp16 tensor-core implicit GEMM (conv2b / conv3a / conv3b) ----
// mma.sync m16n8k16 f16 (f32 accum). BM=128, BK=32 (2 k-slices/stage).
// Smem staged PRE-PERMUTED into fragment layout: A atom = 32 lanes x uint4,
// B atom = 32 lanes x uint2. Conflict-free vector fragment loads.
// Requires CIN % 32 == 0.
template <int CIN, int COUT, int S, int BN>
__global__ void __launch_bounds__(256) conv_mma_f16(
    const float* __restrict__ in, const float* __restrict__ w,
    const float* __restrict__ mout, float* __restrict__ out,
    int Din, int Dout) {
    constexpr int BM = 128;
    constexpr int BK = 32;
    constexpr int T = 27 * CIN / BK;
    constexpr int NTW = BN / 32;           // n8-tiles per warp
    constexpr int ASTG = 2048;             // b32 per A stage (128 rows x 32 k /2)
    constexpr int BSTG = BN * 16;          // b32 per B stage
    constexpr int BU = BN / 32;            // B (k-pair, n-pair) units per thread

    extern __shared__ __align__(16) char smem[];
    int* sB = (int*)smem;
    int* sZ = sB + 128;
    int* sY = sZ + 128;
    int* sX = sY + 128;
    uint32_t* AsP[2] = { (uint32_t*)(smem + 2048), (uint32_t*)(smem + 2048) + ASTG };
    uint32_t* BsP[2] = { (uint32_t*)(smem + 2048) + 2 * ASTG,
                         (uint32_t*)(smem + 2048) + 2 * ASTG + BSTG };

    const int tid = threadIdx.x;
    const int warp = tid >> 5;
    const int lane = tid & 31;
    const int wm = warp & 1;               // 2 warps along M
    const int wn = warp >> 1;              // 4 warps along N
    const int m0 = blockIdx.x * BM;
    const int n0 = blockIdx.y * BN;

    if (tid < BM) {
        int mm = m0 + tid;
        int ow = mm % Dout; int t = mm / Dout;
        int oh = t % Dout; t /= Dout;
        int od = t % Dout; int b = t / Dout;
        sB[tid] = b; sZ[tid] = od * S - 1; sY[tid] = oh * S - 1; sX[tid] = ow * S - 1;
    }
    __syncthreads();

    float acc[4][NTW][4];
    #pragma unroll
    for (int i = 0; i < 4; i++)
        #pragma unroll
        for (int j = 0; j < NTW; j++)
            #pragma unroll
            for (int q = 0; q < 4; q++) acc[i][j][q] = 0.f;

    float4 ra[4];
    float2 rb0[BU], rb1[BU];

    auto loadStage = [&](int st) {
        int k0 = st * BK;
        int tap = k0 / CIN;
        int ci0 = k0 - tap * CIN;
        int tz = tap / 9; int tr = tap - tz * 9;
        int tyy = tr / 3; int txx = tr - tyy * 3;
        #pragma unroll
        for (int r = 0; r < 4; r++) {
            int qi = tid + 256 * r;            // 0..1023: (m, 4k-quad)
            int m = qi >> 3, kq = qi & 7;
            int iz = sZ[m] + tz, iy = sY[m] + tyy, ix = sX[m] + txx;
            float4 v = make_float4(0, 0, 0, 0);
            if ((unsigned)iz < (unsigned)Din && (unsigned)iy < (unsigned)Din &&
                (unsigned)ix < (unsigned)Din) {
                v = *(const float4*)(in +
                    (size_t)(((sB[m] * Din + iz) * Din + iy) * Din + ix) * CIN +
                    ci0 + kq * 4);
            }
            ra[r] = v;
        }
        #pragma unroll
        for (int j = 0; j < BU; j++) {
            int u = tid + 256 * j;             // (kp 0..15, n2 0..BN/2-1)
            int kp = u / (BN / 2);
            int n2 = u % (BN / 2);
            const float* wp = w + (size_t)(k0 + 2 * kp) * COUT + n0 + 2 * n2;
            rb0[j] = *(const float2*)wp;
            rb1[j] = *(const float2*)(wp + COUT);
        }
    };
    auto storeStage = [&](int s) {
        uint32_t* A = AsP[s];
        #pragma unroll
        for (int r = 0; r < 4; r++) {
            int qi = tid + 256 * r;
            int m = qi >> 3, kq = qi & 7;
            int mt = m >> 4, g = m & 7, r8 = (m >> 3) & 1;
            const float* f = (const float*)&ra[r];
            #pragma unroll
            for (int p = 0; p < 2; p++) {
                int k = kq * 4 + 2 * p;
                int ks = k >> 4, kk = k & 15;
                int t = (kk & 7) >> 1;
                int reg = ((kk >= 8) ? 2 : 0) + r8;
                A[(mt * 2 + ks) * 128 + (g * 4 + t) * 4 + reg] =
                    packh2(f[2 * p], f[2 * p + 1]);
            }
        }
        uint32_t* Bp = BsP[s];
        #pragma unroll
        for (int j = 0; j < BU; j++) {
            int u = tid + 256 * j;
            int kp = u / (BN / 2);
            int n2 = u % (BN / 2);
            int ks = kp >> 3, kkp = kp & 7;
            int reg = (kkp >= 4) ? 1 : 0;
            int t = kkp & 3;
            int col = 2 * n2;
            int nt = col >> 3, g = col & 7;
            uint32_t base = (nt * 2 + ks) * 64;
            Bp[base + (g * 4 + t) * 2 + reg] = packh2(rb0[j].x, rb1[j].x);
            Bp[base + ((g + 1) * 4 + t) * 2 + reg] = packh2(rb0[j].y, rb1[j].y);
        }
    };
    auto compute = [&](int s) {
        const uint32_t* A = AsP[s];
        const uint32_t* Bp = BsP[s];
        #pragma unroll
        for (int ks = 0; ks < 2; ks++) {
            uint4 af[4];
            uint2 bf[NTW];
            #pragma unroll
            for (int i = 0; i < 4; i++)
                af[i] = *(const uint4*)(A + ((wm * 4 + i) * 2 + ks) * 128 + lane * 4);
            #pragma unroll
            for (int j = 0; j < NTW; j++)
                bf[j] = *(const uint2*)(Bp + ((wn * NTW + j) * 2 + ks) * 64 + lane * 2);
            #pragma unroll
            for (int i = 0; i < 4; i++)
                #pragma unroll
                for (int j = 0; j < NTW; j++)
                    mma_f16(acc[i][j], (const uint32_t*)&af[i], (const uint32_t*)&bf[j]);
        }
    };

    loadStage(0);
    storeStage(0);
    __syncthreads();

    for (int st = 0; st < T; st++) {
        int s = st & 1;
        bool more = (st + 1) < T;
        if (more) loadStage(st + 1);
        compute(s);
        __syncthreads();
        if (more) { storeStage(s ^ 1); __syncthreads(); }
    }

    // epilogue (C fragment: c0,c1 = row g cols 2t,2t+1; c2,c3 = row g+8)
    const int g = lane >> 2, t = lane & 3;
    #pragma unroll
    for (int i = 0; i < 4; i++) {
        int row0 = m0 + wm * 64 + i * 16 + g;
        int row1 = row0 + 8;
        float mk0 = mout[row0], mk1 = mout[row1];
        #pragma unroll
        for (int j = 0; j < NTW; j++) {
            int col = n0 + (wn * NTW + j) * 8 + t * 2;
            *(float2*)(out + (size_t)row0 * COUT + col) =
                make_float2(acc[i][j][0] * mk0, acc[i][j][1] * mk0);
            *(float2*)(out + (size_t)row1 * COUT + col) =
                make_float2(acc[i][j][2] * mk1, acc[i][j][3] * mk1);
        }
    }
}

// ---------------- BN reductions ----------------
template <int C>
__global__ void __launch_bounds__(256) bn_reduce(const float* __restrict__ y, int nsites,
                                                 float* __restrict__ part) {
    constexpr int GP = C / 4;
    constexpr int NG = 256 / GP;
    int tid = threadIdx.x;
    int g = tid / GP;
    int lane = tid - g * GP;
    int c0 = lane * 4;
    float s0 = 0, s1 = 0, s2 = 0, s3 = 0;
    float q0 = 0, q1 = 0, q2 = 0, q3 = 0;
    for (int site = blockIdx.x * NG + g; site < nsites; site += gridDim.x * NG) {
        float4 v = *(const float4*)(y + (long)site * C + c0);
        s0 += v.x; s1 += v.y; s2 += v.z; s3 += v.w;
        q0 += v.x * v.x; q1 += v.y * v.y; q2 += v.z * v.z; q3 += v.w * v.w;
    }
    __shared__ float sm[NG][C];
    __shared__ float sq[NG][C];
    sm[g][c0 + 0] = s0; sm[g][c0 + 1] = s1; sm[g][c0 + 2] = s2; sm[g][c0 + 3] = s3;
    sq[g][c0 + 0] = q0; sq[g][c0 + 1] = q1; sq[g][c0 + 2] = q2; sq[g][c0 + 3] = q3;
    __syncthreads();
    for (int c = tid; c < C; c += 256) {
        float a = 0, b = 0;
        #pragma unroll 4
        for (int gg = 0; gg < NG; gg++) { a += sm[gg][c]; b += sq[gg][c]; }
        part[blockIdx.x * (2 * C) + c] = a;
        part[blockIdx.x * (2 * C) + C + c] = b;
    }
}

template <int C>
__global__ void __launch_bounds__(512) bn_finalize(
        const float* __restrict__ part, const int* __restrict__ cntp,
        const float* __restrict__ gamma, const float* __restrict__ beta,
        float* __restrict__ scale, float* __restrict__ shift) {
    constexpr int R = 512 / C;
    int c = threadIdx.x % C;
    int r = threadIdx.x / C;
    float s = 0, q = 0;
    for (int nb = r; nb < 128; nb += R) {
        s += part[nb * 2 * C + c];
        q += part[nb * 2 * C + C + c];
    }
    __shared__ float ss[512], qq[512];
    ss[threadIdx.x] = s; qq[threadIdx.x] = q;
    __syncthreads();
    if (r == 0) {
        for (int rr = 1; rr < R; rr++) { s += ss[rr * C + c]; q += qq[rr * C + c]; }
        float cnt = (float)cntp[0];
        float mean = s / cnt;
        float var = q / cnt - mean * mean;
        float sc = gamma[c] * rsqrtf(var + EPSBN);
        scale[c] = sc;
        shift[c] = beta[c] - mean * sc;
    }
}

template <int C>
__global__ void bn_apply(float* __restrict__ y, const float* __restrict__ m,
                         const float* __restrict__ scale, const float* __restrict__ shift,
                         int nsites) {
    __shared__ float sc[C], sh[C];
    for (int i = threadIdx.x; i < C; i += blockDim.x) { sc[i] = scale[i]; sh[i] = shift[i]; }
    __syncthreads();
    long total = (long)nsites * (C / 4);
    long i = (long)blockIdx.x * blockDim.x + threadIdx.x;
    if (i >= total) return;
    float4 v = ((float4*)y)[i];
    int cq = (int)(i % (C / 4)) * 4;
    float mk = m[i / (C / 4)];
    float a;
    a = v.x * sc[cq + 0] + sh[cq + 0]; v.x = (a > 0.f ? a : expm1f(a)) * mk;
    a = v.y * sc[cq + 1] + sh[cq + 1]; v.y = (a > 0.f ? a : expm1f(a)) * mk;
    a = v.z * sc[cq + 2] + sh[cq + 2]; v.z = (a > 0.f ? a : expm1f(a)) * mk;
    a = v.w * sc[cq + 3] + sh[cq + 3]; v.w = (a > 0.f ? a : expm1f(a)) * mk;
    ((float4*)y)[i] = v;
}

// ---------------- global pooling ----------------
__global__ void pool_partial(const float* __restrict__ y, const float* __restrict__ m3,
                             float* __restrict__ ppart, float* __restrict__ cpart) {
    int b = blockIdx.x;
    int g = blockIdx.y;
    int c = threadIdx.x;
    float s = 0;
    int sbase = g * 256;
    for (int k = 0; k < 256; k++) s += y[((long)(b * 4096 + sbase + k)) * 512 + c];
    ppart[(b * 16 + g) * 512 + c] = s;
    __shared__ float red[512];
    red[c] = (c < 256) ? m3[b * 4096 + sbase + c] : 0.f;
    __syncthreads();
    for (int st = 256; st > 0; st >>= 1) {
        if (c < st) red[c] += red[c + st];
        __syncthreads();
    }
    if (c == 0) cpart[b * 16 + g] = red[0];
}

__global__ void pool_final(const float* __restrict__ ppart, const float* __restrict__ cpart,
                           float* __restrict__ pooled) {
    int b = blockIdx.x;
    int c = threadIdx.x;
    float s = 0, cnt = 0;
    for (int g = 0; g < 16; g++) {
        s += ppart[(b * 16 + g) * 512 + c];
        cnt += cpart[b * 16 + g];
    }
    pooled[b * 512 + c] = s / cnt;
}

// ---------------- heads ----------------
__global__ void heads_kernel(const float* __restrict__ pooled,
                             const float* __restrict__ wm, const float* __restrict__ bm,
                             const float* __restrict__ wv, const float* __restrict__ bv,
                             float* __restrict__ out) {
    int b = blockIdx.x;
    int j = threadIdx.x;
    __shared__ float p[512];
    p[j] = pooled[b * 512 + j];
    __syncthreads();
    float sm_ = bm[j], sv = bv[j];
    for (int c = 0; c < 512; c++) {
        float pv = p[c];
        sm_ += pv * wm[c * 512 + j];
        sv += pv * wv[c * 512 + j];
    }
    out[b * 512 + j] = sm_;
    out[2048 + b * 512 + j] = sv;
}

// ---------------- host launcher ----------------
extern "C" void kernel_launch(void* const* d_in, const int* in_sizes, int n_in,
                              void* d_out, int out_size) {
    const float* x    = (const float*)d_in[0];
    const int*   mask = (const int*)d_in[1];
    const float* w1a = (const float*)d_in[2];
    const float* g1a = (const float*)d_in[3];
    const float* b1a = (const float*)d_in[4];
    const float* w1b = (const float*)d_in[5];
    const float* g1b = (const float*)d_in[6];
    const float* b1b = (const float*)d_in[7];
    const float* w2a = (const float*)d_in[8];
    const float* g2a = (const float*)d_in[9];
    const float* b2a = (const float*)d_in[10];
    const float* w2b = (const float*)d_in[11];
    const float* g2b = (const float*)d_in[12];
    const float* b2b = (const float*)d_in[13];
    const float* w3a = (const float*)d_in[14];
    const float* g3a = (const float*)d_in[15];
    const float* b3a = (const float*)d_in[16];
    const float* w3b = (const float*)d_in[17];
    const float* g3b = (const float*)d_in[18];
    const float* b3b = (const float*)d_in[19];
    const float* wm  = (const float*)d_in[20];
    const float* bm  = (const float*)d_in[21];
    const float* wv  = (const float*)d_in[22];
    const float* bv  = (const float*)d_in[23];

    float *bufA, *bufB, *m1, *m2, *m3, *part, *scale, *shift, *ppart, *cpart, *pooled;
    int* cnt;
    cudaGetSymbolAddress((void**)&bufA, g_bufA);
    cudaGetSymbolAddress((void**)&bufB, g_bufB);
    cudaGetSymbolAddress((void**)&m1, g_m1);
    cudaGetSymbolAddress((void**)&m2, g_m2);
    cudaGetSymbolAddress((void**)&m3, g_m3);
    cudaGetSymbolAddress((void**)&cnt, g_cnt);
    cudaGetSymbolAddress((void**)&part, g_part);
    cudaGetSymbolAddress((void**)&scale, g_scale);
    cudaGetSymbolAddress((void**)&shift, g_shift);
    cudaGetSymbolAddress((void**)&ppart, g_ppart);
    cudaGetSymbolAddress((void**)&cpart, g_cpart);
    cudaGetSymbolAddress((void**)&pooled, g_pooled);

    // dynamic smem: 2048 (coords) + 2*8192 (A f16 stages) + 2*BN*64 (B f16 stages)
    const int SMF64  = 2048 + 2 * 8192 + 2 * 64 * 64;    // 26624
    const int SMF128 = 2048 + 2 * 8192 + 2 * 128 * 64;   // 34816
    cudaFuncSetAttribute(conv_mma_f16<64, 64, 1, 64>,
                         cudaFuncAttributeMaxDynamicSharedMemorySize, SMF64);
    cudaFuncSetAttribute(conv_mma_f16<64, 512, 2, 128>,
                         cudaFuncAttributeMaxDynamicSharedMemorySize, SMF128);
    cudaFuncSetAttribute(conv_mma_f16<512, 512, 1, 128>,
                         cudaFuncAttributeMaxDynamicSharedMemorySize, SMF128);

    cudaMemsetAsync(cnt, 0, 3 * sizeof(int));

    // ---- block 1 ----
    pool_mask_kernel<int><<<4096, 256>>>(mask, m1, cnt + 0, 4, 64);
    conv1a_kernel<<<4096, 256>>>(x, mask, w1a, m1, bufA);
    bn_reduce<16><<<128, 256>>>(bufA, 1048576, part);
    bn_finalize<16><<<1, 512>>>(part, cnt + 0, g1a, b1a, scale, shift);
    bn_apply<16><<<(1048576 * 4 + 255) / 256, 256>>>(bufA, m1, scale, shift, 1048576);
    conv1b_kernel<<<2048, 256>>>(bufA, w1b, m1, bufB);
    bn_reduce<16><<<128, 256>>>(bufB, 1048576, part);
    bn_finalize<16><<<1, 512>>>(part, cnt + 0, g1b, b1b, scale, shift);
    bn_apply<16><<<(1048576 * 4 + 255) / 256, 256>>>(bufB, m1, scale, shift, 1048576);

    // ---- block 2 ----
    pool_mask_kernel<float><<<512, 256>>>(m1, m2, cnt + 1, 4, 32);
    conv_igemm2<16, 64, 2, 64><<<dim3(1024, 1), 256>>>(bufB, w2a, m2, bufA, 64, 32);
    bn_reduce<64><<<128, 256>>>(bufA, 131072, part);
    bn_finalize<64><<<1, 512>>>(part, cnt + 1, g2a, b2a, scale, shift);
    bn_apply<64><<<(131072 * 16 + 255) / 256, 256>>>(bufA, m2, scale, shift, 131072);
    conv_mma_f16<64, 64, 1, 64><<<dim3(1024, 1), 256, SMF64>>>(bufA, w2b, m2, bufB, 32, 32);
    bn_reduce<64><<<128, 256>>>(bufB, 131072, part);
    bn_finalize<64><<<1, 512>>>(part, cnt + 1, g2b, b2b, scale, shift);
    bn_apply<64><<<(131072 * 16 + 255) / 256, 256>>>(bufB, m2, scale, shift, 131072);

    // ---- block 3 ----
    pool_mask_kernel<float><<<64, 256>>>(m2, m3, cnt + 2, 4, 16);
    conv_mma_f16<64, 512, 2, 128><<<dim3(128, 4), 256, SMF128>>>(bufB, w3a, m3, bufA, 32, 16);
    bn_reduce<512><<<128, 256>>>(bufA, 16384, part);
    bn_finalize<512><<<1, 512>>>(part, cnt + 2, g3a, b3a, scale, shift);
    bn_apply<512><<<(16384 * 128 + 255) / 256, 256>>>(bufA, m3, scale, shift, 16384);
    conv_mma_f16<512, 512, 1, 128><<<dim3(128, 4), 256, SMF128>>>(bufA, w3b, m3, bufB, 16, 16);
    bn_reduce<512><<<128, 256>>>(bufB, 16384, part);
    bn_finalize<512><<<1, 512>>>(part, cnt + 2, g3b, b3b, scale, shift);
    bn_apply<512><<<(16384 * 128 + 255) / 256, 256>>>(bufB, m3, scale, shift, 16384);

    // ---- global pooling + heads ----
    pool_partial<<<dim3(4, 16), 512>>>(bufB, m3, ppart, cpart);
    pool_final<<<4, 512>>>(ppart, cpart, pooled);
    heads_kernel<<<4, 512>>>(pooled, wm, bm, wv, bv, (float*)d_out);

    (void)in_sizes; (void)n_in; (void)out_size;
}

// round 7
// speedup vs baseline: 3.6282x; 1.7715x over previous
#include <cuda_runtime.h>
#include <cuda_fp16.h>
#include <math.h>
#include <stdint.h>

typedef unsigned long long ull;

// ---------------- packed f32x2 helpers ----------------
__device__ __forceinline__ ull pack2(float lo, float hi) {
    ull r; asm("mov.b64 %0, {%1, %2};" : "=l"(r) : "f"(lo), "f"(hi)); return r;
}
__device__ __forceinline__ float2 unpack2(ull v) {
    float2 f; asm("mov.b64 {%0, %1}, %2;" : "=f"(f.x), "=f"(f.y) : "l"(v)); return f;
}
__device__ __forceinline__ void ffma2(ull& d, ull a, ull b) {
    asm("fma.rn.f32x2 %0, %1, %2, %3;" : "=l"(d) : "l"(a), "l"(b), "l"(d));
}

// ---------------- fp16 mma helpers ----------------
__device__ __forceinline__ uint32_t packh2(float lo, float hi) {
    __half2 h = __floats2half2_rn(lo, hi);
    return *(uint32_t*)&h;
}
__device__ __forceinline__ void mma_f16(float* c, const uint32_t* a, const uint32_t* b) {
    asm volatile(
        "mma.sync.aligned.m16n8k16.row.col.f32.f16.f16.f32 "
        "{%0,%1,%2,%3}, {%4,%5,%6,%7}, {%8,%9}, {%0,%1,%2,%3};"
        : "+f"(c[0]), "+f"(c[1]), "+f"(c[2]), "+f"(c[3])
        : "r"(a[0]), "r"(a[1]), "r"(a[2]), "r"(a[3]), "r"(b[0]), "r"(b[1]));
}

// ---------------- static scratch ----------------
__device__ float g_bufA[16777216];
__device__ float g_bufB[16777216];
__device__ __align__(16) __half g_hbuf[16777216];     // fp16 activations
__device__ __align__(16) uint32_t g_hw[7604224];      // pre-packed fp16 weight fragments
__device__ float g_m1[1048576];
__device__ float g_m2[131072];
__device__ float g_m3[16384];
__device__ int   g_cnt[3];
__device__ float g_part[128 * 1024];
__device__ float g_scale[512];
__device__ float g_shift[512];
__device__ float g_ppart[4 * 16 * 512];
__device__ float g_cpart[4 * 16];
__device__ float g_pooled[4 * 512];

#define EPSBN 1e-5f

// ---------------- weight fragment prep ----------------
// layout: idx = ((((st*2+ks)*NT + nt)*32) + lane)*2 + reg
// value  = packh2(w[k][n], w[k+1][n]); k = st*32 + ks*16 + 2*(reg*4+t); n = nt*8+g
template <int COUT>
__global__ void wprep_kernel(const float* __restrict__ w, uint32_t* __restrict__ whp,
                             int total, int Kmax) {
    int idx = blockIdx.x * 256 + threadIdx.x;
    if (idx >= total) return;
    constexpr int NT = COUT / 8;
    int reg = idx & 1;
    int lane = (idx >> 1) & 31;
    int rest = idx >> 6;
    int nt = rest % NT;
    int sk = rest / NT;
    int ks = sk & 1;
    int st = sk >> 1;
    int g = lane >> 2, t = lane & 3;
    int k = st * 32 + ks * 16 + 2 * (reg * 4 + t);
    int n = nt * 8 + g;
    uint32_t v = 0;
    if (k < Kmax)
        v = packh2(w[(size_t)k * COUT + n], w[(size_t)(k + 1) * COUT + n]);
    whp[idx] = v;
}

// ---------------- mask pooling + active count ----------------
template <typename T>
__global__ void pool_mask_kernel(const T* __restrict__ min_, float* __restrict__ mout,
                                 int* __restrict__ cnt, int B, int Dout) {
    int Din = Dout * 2;
    int M = B * Dout * Dout * Dout;
    int site = blockIdx.x * blockDim.x + threadIdx.x;
    int active = 0;
    if (site < M) {
        int ow = site % Dout; int t = site / Dout;
        int oh = t % Dout; t /= Dout;
        int od = t % Dout; int b = t / Dout;
        int iz0 = od * 2, iy0 = oh * 2, ix0 = ow * 2;
        bool a = false;
        #pragma unroll
        for (int dz = 0; dz < 2; dz++)
            #pragma unroll
            for (int dy = 0; dy < 2; dy++)
                #pragma unroll
                for (int dx = 0; dx < 2; dx++) {
                    T v = min_[(((long)(b * Din + iz0 + dz) * Din + iy0 + dy) * Din) + ix0 + dx];
                    a = a || (v != (T)0);
                }
        mout[site] = a ? 1.f : 0.f;
        active = a ? 1 : 0;
    }
    unsigned bal = __ballot_sync(0xffffffffu, active);
    __shared__ int ws[8];
    if ((threadIdx.x & 31) == 0) ws[threadIdx.x >> 5] = __popc(bal);
    __syncthreads();
    if (threadIdx.x == 0) {
        int t = 0;
        for (int i = 0; i < (int)(blockDim.x >> 5); i++) t += ws[i];
        atomicAdd(cnt, t);
    }
}

// ---------------- conv1a ----------------
__global__ void __launch_bounds__(256) conv1a_kernel(
    const float* __restrict__ x, const int* __restrict__ mask,
    const float* __restrict__ w, const float* __restrict__ m1, float* __restrict__ y) {
    __shared__ float wsh[432];
    for (int i = threadIdx.x; i < 432; i += 256) wsh[i] = w[i];
    __syncthreads();
    int site = blockIdx.x * 256 + threadIdx.x;
    int ow = site & 63; int t = site >> 6;
    int oh = t & 63; t >>= 6;
    int od = t & 63; int b = t >> 6;
    float acc[16];
    #pragma unroll
    for (int c = 0; c < 16; c++) acc[c] = 0.f;
    #pragma unroll
    for (int tz = 0; tz < 3; tz++) {
        int iz = od * 2 - 1 + tz;
        if ((unsigned)iz >= 128u) continue;
        #pragma unroll
        for (int ty = 0; ty < 3; ty++) {
            int iy = oh * 2 - 1 + ty;
            if ((unsigned)iy >= 128u) continue;
            #pragma unroll
            for (int tx = 0; tx < 3; tx++) {
                int ix = ow * 2 - 1 + tx;
                if ((unsigned)ix >= 128u) continue;
                int idx = ((b * 128 + iz) * 128 + iy) * 128 + ix;
                if (mask[idx]) {
                    float v = x[idx];
                    int tap = (tz * 3 + ty) * 3 + tx;
                    #pragma unroll
                    for (int c = 0; c < 16; c++) acc[c] += v * wsh[tap * 16 + c];
                }
            }
        }
    }
    float mk = m1[site];
    float* o = y + (long)site * 16;
    #pragma unroll
    for (int q = 0; q < 4; q++) {
        float4 v = make_float4(acc[q*4]*mk, acc[q*4+1]*mk, acc[q*4+2]*mk, acc[q*4+3]*mk);
        *(float4*)(o + q * 4) = v;
    }
}

// ---------------- conv1b: f32x2 ----------------
__global__ void __launch_bounds__(256) conv1b_kernel(
    const float* __restrict__ in, const float* __restrict__ w,
    const float* __restrict__ m, float* __restrict__ out) {
    __shared__ __align__(16) float wsh[6912];
    for (int i = threadIdx.x; i < 6912; i += 256) wsh[i] = w[i];
    __syncthreads();
    int pair = blockIdx.x * 256 + threadIdx.x;
    int s0 = pair * 2;
    int ow = s0 & 63; int t = s0 >> 6;
    int oh = t & 63; t >>= 6;
    int od = t & 63; int b = t >> 6;
    ull acc0p[8], acc1p[8];
    #pragma unroll
    for (int h = 0; h < 8; h++) { acc0p[h] = 0ull; acc1p[h] = 0ull; }
    #pragma unroll
    for (int tz = 0; tz < 3; tz++) {
        int iz = od - 1 + tz;
        if ((unsigned)iz >= 64u) continue;
        #pragma unroll
        for (int ty = 0; ty < 3; ty++) {
            int iy = oh - 1 + ty;
            if ((unsigned)iy >= 64u) continue;
            int rowbase = ((b * 64 + iz) * 64 + iy) * 64;
            #pragma unroll
            for (int tx = 0; tx < 3; tx++) {
                int ix0 = ow - 1 + tx;
                int ix1 = ix0 + 1;
                int tap = (tz * 3 + ty) * 3 + tx;
                const float* wp = wsh + tap * 256;
                bool ok0 = (unsigned)ix0 < 64u;
                bool ok1 = (unsigned)ix1 < 64u;
                float4 v0q[4], v1q[4];
                #pragma unroll
                for (int q = 0; q < 4; q++) {
                    v0q[q] = ok0 ? *(const float4*)(in + (long)(rowbase + ix0) * 16 + q * 4)
                                 : make_float4(0, 0, 0, 0);
                    v1q[q] = ok1 ? *(const float4*)(in + (long)(rowbase + ix1) * 16 + q * 4)
                                 : make_float4(0, 0, 0, 0);
                }
                const float* v0 = (const float*)v0q;
                const float* v1 = (const float*)v1q;
                #pragma unroll
                for (int ci = 0; ci < 16; ci++) {
                    ull a0d = pack2(v0[ci], v0[ci]);
                    ull a1d = pack2(v1[ci], v1[ci]);
                    const ull* wrow = (const ull*)(wp + ci * 16);
                    #pragma unroll
                    for (int h = 0; h < 8; h++) {
                        ull wv = wrow[h];
                        ffma2(acc0p[h], a0d, wv);
                        ffma2(acc1p[h], a1d, wv);
                    }
                }
            }
        }
    }
    float mk0 = m[s0], mk1 = m[s0 + 1];
    #pragma unroll
    for (int q = 0; q < 4; q++) {
        float2 e0 = unpack2(acc0p[2*q]), e1 = unpack2(acc0p[2*q+1]);
        *(float4*)(out + (long)s0 * 16 + q * 4) =
            make_float4(e0.x*mk0, e0.y*mk0, e1.x*mk0, e1.y*mk0);
        float2 f0 = unpack2(acc1p[2*q]), f1 = unpack2(acc1p[2*q+1]);
        *(float4*)(out + (long)(s0 + 1) * 16 + q * 4) =
            make_float4(f0.x*mk1, f0.y*mk1, f1.x*mk1, f1.y*mk1);
    }
}

// ---------------- fp16 tensor-core implicit GEMM (conv2a/2b/3a/3b) ----------------
// Input activations fp16; weights pre-packed into fragment order (whp).
// BM=128, BK=32 (2 k16 slices/stage). Handles CIN<32 via per-unit tap math and
// zero-padded last stage (T = ceil(27*CIN/32)).
template <int CIN, int COUT, int S, int BN>
__global__ void __launch_bounds__(256) conv_mma_f16(
    const __half* __restrict__ in, const uint32_t* __restrict__ whp,
    const float* __restrict__ mout, float* __restrict__ out,
    int Din, int Dout) {
    constexpr int BM = 128;
    constexpr int KTOT = 27 * CIN;
    constexpr int T = (KTOT + 31) / 32;
    constexpr int NTW = BN / 32;          // n8-tiles per warp
    constexpr int NTG = COUT / 8;         // global n8-tiles
    constexpr int ASTG = 2048;            // uint32 per A stage
    constexpr int BSTG = BN * 16;         // uint32 per B stage
    constexpr int BQ4 = BN / 64;          // uint4 per thread for B stage

    extern __shared__ __align__(16) char smem[];
    int* sB = (int*)smem;
    int* sZ = sB + 128;
    int* sY = sZ + 128;
    int* sX = sY + 128;
    uint32_t* AsP[2] = { (uint32_t*)(smem + 2048), (uint32_t*)(smem + 2048) + ASTG };
    uint32_t* BsP[2] = { (uint32_t*)(smem + 2048) + 2 * ASTG,
                         (uint32_t*)(smem + 2048) + 2 * ASTG + BSTG };

    const int tid = threadIdx.x;
    const int warp = tid >> 5;
    const int lane = tid & 31;
    const int wm = warp & 1;
    const int wn = warp >> 1;
    const int m0 = blockIdx.x * BM;
    const int n0 = blockIdx.y * BN;
    const int byNT = blockIdx.y * (BN / 8);

    if (tid < BM) {
        int mm = m0 + tid;
        int ow = mm % Dout; int t = mm / Dout;
        int oh = t % Dout; t /= Dout;
        int od = t % Dout; int b = t / Dout;
        sB[tid] = b; sZ[tid] = od * S - 1; sY[tid] = oh * S - 1; sX[tid] = ow * S - 1;
    }
    __syncthreads();

    float acc[4][NTW][4];
    #pragma unroll
    for (int i = 0; i < 4; i++)
        #pragma unroll
        for (int j = 0; j < NTW; j++)
            #pragma unroll
            for (int q = 0; q < 4; q++) acc[i][j][q] = 0.f;

    uint4 ra[2], rbv[BQ4];

    auto loadStage = [&](int st) {
        int k0 = st * 32;
        #pragma unroll
        for (int r = 0; r < 2; r++) {
            int u = tid + 256 * r;        // (m, kg): m = u>>2, kg = u&3 (8 halves each)
            int m = u >> 2, kg = u & 3;
            int k = k0 + kg * 8;
            uint4 v = make_uint4(0, 0, 0, 0);
            if (k < KTOT) {
                int tap = k / CIN, ci = k % CIN;
                int tz = tap / 9; int tr = tap - tz * 9;
                int tyy = tr / 3; int txx = tr - tyy * 3;
                int iz = sZ[m] + tz, iy = sY[m] + tyy, ix = sX[m] + txx;
                if ((unsigned)iz < (unsigned)Din && (unsigned)iy < (unsigned)Din &&
                    (unsigned)ix < (unsigned)Din)
                    v = *(const uint4*)(in +
                        (size_t)(((sB[m] * Din + iz) * Din + iy) * Din + ix) * CIN + ci);
            }
            ra[r] = v;
        }
        #pragma unroll
        for (int r = 0; r < BQ4; r++) {
            int u = tid + 256 * r;        // uint4 index; per-ks chunk = BN*2 uint4
            int ks = u / (BN * 2);
            int ci4 = u - ks * (BN * 2);
            rbv[r] = ((const uint4*)whp)[(size_t)((st * 2 + ks) * NTG + byNT) * 16 + ci4];
        }
    };
    auto storeStage = [&](int s) {
        uint32_t* A = AsP[s];
        #pragma unroll
        for (int r = 0; r < 2; r++) {
            int u = tid + 256 * r;
            int m = u >> 2, kg = u & 3;
            int mt = m >> 4, g = m & 7, r8 = (m >> 3) & 1;
            int ks = kg >> 1;
            int reg = ((kg & 1) ? 2 : 0) + r8;
            uint32_t base = (uint32_t)(mt * 2 + ks) * 128 + g * 16 + reg;
            const uint32_t* f = (const uint32_t*)&ra[r];
            A[base + 0]  = f[0];
            A[base + 4]  = f[1];
            A[base + 8]  = f[2];
            A[base + 12] = f[3];
        }
        uint4* Bp = (uint4*)BsP[s];
        #pragma unroll
        for (int r = 0; r < BQ4; r++)
            Bp[tid + 256 * r] = rbv[r];
    };
    auto compute = [&](int s) {
        const uint32_t* A = AsP[s];
        const uint32_t* Bp = BsP[s];
        #pragma unroll
        for (int ks = 0; ks < 2; ks++) {
            uint4 af[4];
            uint2 bf[NTW];
            #pragma unroll
            for (int i = 0; i < 4; i++)
                af[i] = *(const uint4*)(A + ((wm * 4 + i) * 2 + ks) * 128 + lane * 4);
            #pragma unroll
            for (int j = 0; j < NTW; j++)
                bf[j] = *(const uint2*)(Bp + (ks * (BN / 8) + wn * NTW + j) * 64 + lane * 2);
            #pragma unroll
            for (int i = 0; i < 4; i++)
                #pragma unroll
                for (int j = 0; j < NTW; j++)
                    mma_f16(acc[i][j], (const uint32_t*)&af[i], (const uint32_t*)&bf[j]);
        }
    };

    loadStage(0);
    storeStage(0);
    __syncthreads();

    for (int st = 0; st < T; st++) {
        int s = st & 1;
        bool more = (st + 1) < T;
        if (more) loadStage(st + 1);
        compute(s);
        __syncthreads();
        if (more) { storeStage(s ^ 1); __syncthreads(); }
    }

    const int g = lane >> 2, t = lane & 3;
    #pragma unroll
    for (int i = 0; i < 4; i++) {
        int row0 = m0 + wm * 64 + i * 16 + g;
        int row1 = row0 + 8;
        float mk0 = mout[row0], mk1 = mout[row1];
        #pragma unroll
        for (int j = 0; j < NTW; j++) {
            int col = n0 + (wn * NTW + j) * 8 + t * 2;
            *(float2*)(out + (size_t)row0 * COUT + col) =
                make_float2(acc[i][j][0] * mk0, acc[i][j][1] * mk0);
            *(float2*)(out + (size_t)row1 * COUT + col) =
                make_float2(acc[i][j][2] * mk1, acc[i][j][3] * mk1);
        }
    }
}

// ---------------- BN reductions ----------------
template <int C>
__global__ void __launch_bounds__(256) bn_reduce(const float* __restrict__ y, int nsites,
                                                 float* __restrict__ part) {
    constexpr int GP = C / 4;
    constexpr int NG = 256 / GP;
    int tid = threadIdx.x;
    int g = tid / GP;
    int lane = tid - g * GP;
    int c0 = lane * 4;
    float s0 = 0, s1 = 0, s2 = 0, s3 = 0;
    float q0 = 0, q1 = 0, q2 = 0, q3 = 0;
    for (int site = blockIdx.x * NG + g; site < nsites; site += gridDim.x * NG) {
        float4 v = *(const float4*)(y + (long)site * C + c0);
        s0 += v.x; s1 += v.y; s2 += v.z; s3 += v.w;
        q0 += v.x * v.x; q1 += v.y * v.y; q2 += v.z * v.z; q3 += v.w * v.w;
    }
    __shared__ float sm[NG][C];
    __shared__ float sq[NG][C];
    sm[g][c0 + 0] = s0; sm[g][c0 + 1] = s1; sm[g][c0 + 2] = s2; sm[g][c0 + 3] = s3;
    sq[g][c0 + 0] = q0; sq[g][c0 + 1] = q1; sq[g][c0 + 2] = q2; sq[g][c0 + 3] = q3;
    __syncthreads();
    for (int c = tid; c < C; c += 256) {
        float a = 0, b = 0;
        #pragma unroll 4
        for (int gg = 0; gg < NG; gg++) { a += sm[gg][c]; b += sq[gg][c]; }
        part[blockIdx.x * (2 * C) + c] = a;
        part[blockIdx.x * (2 * C) + C + c] = b;
    }
}

template <int C>
__global__ void __launch_bounds__(512) bn_finalize(
        const float* __restrict__ part, const int* __restrict__ cntp,
        const float* __restrict__ gamma, const float* __restrict__ beta,
        float* __restrict__ scale, float* __restrict__ shift) {
    constexpr int R = 512 / C;
    int c = threadIdx.x % C;
    int r = threadIdx.x / C;
    float s = 0, q = 0;
    for (int nb = r; nb < 128; nb += R) {
        s += part[nb * 2 * C + c];
        q += part[nb * 2 * C + C + c];
    }
    __shared__ float ss[512], qq[512];
    ss[threadIdx.x] = s; qq[threadIdx.x] = q;
    __syncthreads();
    if (r == 0) {
        for (int rr = 1; rr < R; rr++) { s += ss[rr * C + c]; q += qq[rr * C + c]; }
        float cnt = (float)cntp[0];
        float mean = s / cnt;
        float var = q / cnt - mean * mean;
        float sc = gamma[c] * rsqrtf(var + EPSBN);
        scale[c] = sc;
        shift[c] = beta[c] - mean * sc;
    }
}

// fp32 in-place BN+ELU (used where next consumer needs fp32)
template <int C>
__global__ void bn_apply(float* __restrict__ y, const float* __restrict__ m,
                         const float* __restrict__ scale, const float* __restrict__ shift,
                         int nsites) {
    __shared__ float sc[C], sh[C];
    for (int i = threadIdx.x; i < C; i += blockDim.x) { sc[i] = scale[i]; sh[i] = shift[i]; }
    __syncthreads();
    long total = (long)nsites * (C / 4);
    long i = (long)blockIdx.x * blockDim.x + threadIdx.x;
    if (i >= total) return;
    float4 v = ((float4*)y)[i];
    int cq = (int)(i % (C / 4)) * 4;
    float mk = m[i / (C / 4)];
    float a;
    a = v.x * sc[cq + 0] + sh[cq + 0]; v.x = (a > 0.f ? a : expm1f(a)) * mk;
    a = v.y * sc[cq + 1] + sh[cq + 1]; v.y = (a > 0.f ? a : expm1f(a)) * mk;
    a = v.z * sc[cq + 2] + sh[cq + 2]; v.z = (a > 0.f ? a : expm1f(a)) * mk;
    a = v.w * sc[cq + 3] + sh[cq + 3]; v.w = (a > 0.f ? a : expm1f(a)) * mk;
    ((float4*)y)[i] = v;
}

// BN+ELU writing fp16 (for mma-conv inputs)
template <int C>
__global__ void bn_apply_h(const float* __restrict__ y, __half* __restrict__ ho,
                           const float* __restrict__ m,
                           const float* __restrict__ scale, const float* __restrict__ shift,
                           int nsites) {
    __shared__ float sc[C], sh[C];
    for (int i = threadIdx.x; i < C; i += blockDim.x) { sc[i] = scale[i]; sh[i] = shift[i]; }
    __syncthreads();
    long total = (long)nsites * (C / 4);
    long i = (long)blockIdx.x * blockDim.x + threadIdx.x;
    if (i >= total) return;
    float4 v = ((const float4*)y)[i];
    int cq = (int)(i % (C / 4)) * 4;
    float mk = m[i / (C / 4)];
    float a;
    a = v.x * sc[cq + 0] + sh[cq + 0]; v.x = (a > 0.f ? a : expm1f(a)) * mk;
    a = v.y * sc[cq + 1] + sh[cq + 1]; v.y = (a > 0.f ? a : expm1f(a)) * mk;
    a = v.z * sc[cq + 2] + sh[cq + 2]; v.z = (a > 0.f ? a : expm1f(a)) * mk;
    a = v.w * sc[cq + 3] + sh[cq + 3]; v.w = (a > 0.f ? a : expm1f(a)) * mk;
    uint2 o;
    o.x = packh2(v.x, v.y);
    o.y = packh2(v.z, v.w);
    ((uint2*)ho)[i] = o;
}

// ---------------- global pooling ----------------
__global__ void pool_partial(const float* __restrict__ y, const float* __restrict__ m3,
                             float* __restrict__ ppart, float* __restrict__ cpart) {
    int b = blockIdx.x;
    int g = blockIdx.y;
    int c = threadIdx.x;
    float s = 0;
    int sbase = g * 256;
    for (int k = 0; k < 256; k++) s += y[((long)(b * 4096 + sbase + k)) * 512 + c];
    ppart[(b * 16 + g) * 512 + c] = s;
    __shared__ float red[512];
    red[c] = (c < 256) ? m3[b * 4096 + sbase + c] : 0.f;
    __syncthreads();
    for (int st = 256; st > 0; st >>= 1) {
        if (c < st) red[c] += red[c + st];
        __syncthreads();
    }
    if (c == 0) cpart[b * 16 + g] = red[0];
}

__global__ void pool_final(const float* __restrict__ ppart, const float* __restrict__ cpart,
                           float* __restrict__ pooled) {
    int b = blockIdx.x;
    int c = threadIdx.x;
    float s = 0, cnt = 0;
    for (int g = 0; g < 16; g++) {
        s += ppart[(b * 16 + g) * 512 + c];
        cnt += cpart[b * 16 + g];
    }
    pooled[b * 512 + c] = s / cnt;
}

// ---------------- heads ----------------
__global__ void heads_kernel(const float* __restrict__ pooled,
                             const float* __restrict__ wm, const float* __restrict__ bm,
                             const float* __restrict__ wv, const float* __restrict__ bv,
                             float* __restrict__ out) {
    int b = blockIdx.x;
    int j = threadIdx.x;
    __shared__ float p[512];
    p[j] = pooled[b * 512 + j];
    __syncthreads();
    float sm_ = bm[j], sv = bv[j];
    for (int c = 0; c < 512; c++) {
        float pv = p[c];
        sm_ += pv * wm[c * 512 + j];
        sv += pv * wv[c * 512 + j];
    }
    out[b * 512 + j] = sm_;
    out[2048 + b * 512 + j] = sv;
}

// ---------------- host launcher ----------------
extern "C" void kernel_launch(void* const* d_in, const int* in_sizes, int n_in,
                              void* d_out, int out_size) {
    const float* x    = (const float*)d_in[0];
    const int*   mask = (const int*)d_in[1];
    const float* w1a = (const float*)d_in[2];
    const float* g1a = (const float*)d_in[3];
    const float* b1a = (const float*)d_in[4];
    const float* w1b = (const float*)d_in[5];
    const float* g1b = (const float*)d_in[6];
    const float* b1b = (const float*)d_in[7];
    const float* w2a = (const float*)d_in[8];
    const float* g2a = (const float*)d_in[9];
    const float* b2a = (const float*)d_in[10];
    const float* w2b = (const float*)d_in[11];
    const float* g2b = (const float*)d_in[12];
    const float* b2b = (const float*)d_in[13];
    const float* w3a = (const float*)d_in[14];
    const float* g3a = (const float*)d_in[15];
    const float* b3a = (const float*)d_in[16];
    const float* w3b = (const float*)d_in[17];
    const float* g3b = (const float*)d_in[18];
    const float* b3b = (const float*)d_in[19];
    const float* wm  = (const float*)d_in[20];
    const float* bm  = (const float*)d_in[21];
    const float* wv  = (const float*)d_in[22];
    const float* bv  = (const float*)d_in[23];

    float *bufA, *bufB, *m1, *m2, *m3, *part, *scale, *shift, *ppart, *cpart, *pooled;
    __half* hbuf;
    uint32_t* hw;
    int* cnt;
    cudaGetSymbolAddress((void**)&bufA, g_bufA);
    cudaGetSymbolAddress((void**)&bufB, g_bufB);
    cudaGetSymbolAddress((void**)&hbuf, g_hbuf);
    cudaGetSymbolAddress((void**)&hw, g_hw);
    cudaGetSymbolAddress((void**)&m1, g_m1);
    cudaGetSymbolAddress((void**)&m2, g_m2);
    cudaGetSymbolAddress((void**)&m3, g_m3);
    cudaGetSymbolAddress((void**)&cnt, g_cnt);
    cudaGetSymbolAddress((void**)&part, g_part);
    cudaGetSymbolAddress((void**)&scale, g_scale);
    cudaGetSymbolAddress((void**)&shift, g_shift);
    cudaGetSymbolAddress((void**)&ppart, g_ppart);
    cudaGetSymbolAddress((void**)&cpart, g_cpart);
    cudaGetSymbolAddress((void**)&pooled, g_pooled);

    // weight fragment prep offsets/sizes (idx units)
    const int N2A = 28672,  O2A = 0;
    const int N2B = 55296,  O2B = O2A + N2A;
    const int N3A = 442368, O3A = O2B + N2B;
    const int N3B = 7077888, O3B = O3A + N3A;

    const int SMF64  = 2048 + 2 * 8192 + 2 * 64 * 64;    // 26624
    const int SMF128 = 2048 + 2 * 8192 + 2 * 128 * 64;   // 34816
    cudaFuncSetAttribute(conv_mma_f16<16, 64, 2, 64>,
                         cudaFuncAttributeMaxDynamicSharedMemorySize, SMF64);
    cudaFuncSetAttribute(conv_mma_f16<64, 64, 1, 64>,
                         cudaFuncAttributeMaxDynamicSharedMemorySize, SMF64);
    cudaFuncSetAttribute(conv_mma_f16<64, 512, 2, 128>,
                         cudaFuncAttributeMaxDynamicSharedMemorySize, SMF128);
    cudaFuncSetAttribute(conv_mma_f16<512, 512, 1, 128>,
                         cudaFuncAttributeMaxDynamicSharedMemorySize, SMF128);

    cudaMemsetAsync(cnt, 0, 3 * sizeof(int));

    // ---- weight prep ----
    wprep_kernel<64><<<(N2A + 255) / 256, 256>>>(w2a, hw + O2A, N2A, 432);
    wprep_kernel<64><<<(N2B + 255) / 256, 256>>>(w2b, hw + O2B, N2B, 1728);
    wprep_kernel<512><<<(N3A + 255) / 256, 256>>>(w3a, hw + O3A, N3A, 1728);
    wprep_kernel<512><<<(N3B + 255) / 256, 256>>>(w3b, hw + O3B, N3B, 13824);

    // ---- block 1 ----
    pool_mask_kernel<int><<<4096, 256>>>(mask, m1, cnt + 0, 4, 64);
    conv1a_kernel<<<4096, 256>>>(x, mask, w1a, m1, bufA);
    bn_reduce<16><<<128, 256>>>(bufA, 1048576, part);
    bn_finalize<16><<<1, 512>>>(part, cnt + 0, g1a, b1a, scale, shift);
    bn_apply<16><<<(1048576 * 4 + 255) / 256, 256>>>(bufA, m1, scale, shift, 1048576);
    conv1b_kernel<<<2048, 256>>>(bufA, w1b, m1, bufB);
    bn_reduce<16><<<128, 256>>>(bufB, 1048576, part);
    bn_finalize<16><<<1, 512>>>(part, cnt + 0, g1b, b1b, scale, shift);
    bn_apply_h<16><<<(1048576 * 4 + 255) / 256, 256>>>(bufB, hbuf, m1, scale, shift, 1048576);

    // ---- block 2 ----
    pool_mask_kernel<float><<<512, 256>>>(m1, m2, cnt + 1, 4, 32);
    conv_mma_f16<16, 64, 2, 64><<<dim3(1024, 1), 256, SMF64>>>(hbuf, hw + O2A, m2, bufA, 64, 32);
    bn_reduce<64><<<128, 256>>>(bufA, 131072, part);
    bn_finalize<64><<<1, 512>>>(part, cnt + 1, g2a, b2a, scale, shift);
    bn_apply_h<64><<<(131072 * 16 + 255) / 256, 256>>>(bufA, hbuf, m2, scale, shift, 131072);
    conv_mma_f16<64, 64, 1, 64><<<dim3(1024, 1), 256, SMF64>>>(hbuf, hw + O2B, m2, bufB, 32, 32);
    bn_reduce<64><<<128, 256>>>(bufB, 131072, part);
    bn_finalize<64><<<1, 512>>>(part, cnt + 1, g2b, b2b, scale, shift);
    bn_apply_h<64><<<(131072 * 16 + 255) / 256, 256>>>(bufB, hbuf, m2, scale, shift, 131072);

    // ---- block 3 ----
    pool_mask_kernel<float><<<64, 256>>>(m2, m3, cnt + 2, 4, 16);
    conv_mma_f16<64, 512, 2, 128><<<dim3(128, 4), 256, SMF128>>>(hbuf, hw + O3A, m3, bufA, 32, 16);
    bn_reduce<512><<<128, 256>>>(bufA, 16384, part);
    bn_finalize<512><<<1, 512>>>(part, cnt + 2, g3a, b3a, scale, shift);
    bn_apply_h<512><<<(16384 * 128 + 255) / 256, 256>>>(bufA, hbuf, m3, scale, shift, 16384);
    conv_mma_f16<512, 512, 1, 128><<<dim3(128, 4), 256, SMF128>>>(hbuf, hw + O3B, m3, bufB, 16, 16);
    bn_reduce<512><<<128, 256>>>(bufB, 16384, part);
    bn_finalize<512><<<1, 512>>>(part, cnt + 2, g3b, b3b, scale, shift);
    bn_apply<512><<<(16384 * 128 + 255) / 256, 256>>>(bufB, m3, scale, shift, 16384);

    // ---- global pooling + heads ----
    pool_partial<<<dim3(4, 16), 512>>>(bufB, m3, ppart, cpart);
    pool_final<<<4, 512>>>(ppart, cpart, pooled);
    heads_kernel<<<4, 512>>>(pooled, wm, bm, wv, bv, (float*)d_out);

    (void)in_sizes; (void)n_in; (void)out_size;
}